// round 11
// baseline (speedup 1.0000x reference)
#include <cuda_runtime.h>
#include <cuda_fp16.h>
#include <mma.h>
#include <math.h>

using namespace nvcuda;

#define NN   100000
#define EE   500000
#define TT   8
#define MSGD 64
#define HIDD 64
#define CC   16

typedef unsigned long long ull;

// ---------------------------------------------------------------------------
// Device scratch
// ---------------------------------------------------------------------------
__device__ __align__(16) float g_reduced[(size_t)NN * MSGD];
__device__ int g_counts[TT];
__device__ int g_cursor[TT];
__device__ int g_src_s[EE];
__device__ int g_dst_s[EE];

// ---------------------------------------------------------------------------
// Packed fp32x2 helpers (Blackwell FFMA2)
// ---------------------------------------------------------------------------
__device__ __forceinline__ void fma2(ull& d, ull a, ull b) {
    asm volatile("fma.rn.f32x2 %0, %1, %2, %0;" : "+l"(d) : "l"(a), "l"(b));
}
__device__ __forceinline__ float2 asf2(ull v) {
    float2 r;
    asm("mov.b64 {%0, %1}, %2;" : "=f"(r.x), "=f"(r.y) : "l"(v));
    return r;
}
__device__ __forceinline__ float fast_sigmoid(float x) {
    return __fdividef(1.f, 1.f + __expf(-x));
}
__device__ __forceinline__ float fast_tanh(float x) {
    return 1.f - __fdividef(2.f, __expf(2.f * x) + 1.f);
}

// ---------------------------------------------------------------------------
// Kernel 0: zero reduction buffer + reset counters (separate launch from
// histogram adds — launch boundary is the grid-wide ordering point).
// ---------------------------------------------------------------------------
__global__ void zero_kernel() {
    int i = blockIdx.x * blockDim.x + threadIdx.x;
    if (i < NN * MSGD / 4) {
        reinterpret_cast<float4*>(g_reduced)[i] = make_float4(0.f, 0.f, 0.f, 0.f);
    }
    if (blockIdx.x == 0 && threadIdx.x < TT) {
        g_counts[threadIdx.x] = 0;
        g_cursor[threadIdx.x] = 0;
    }
}

// ---------------------------------------------------------------------------
// Kernel 1: per-block histogram of edge types
// ---------------------------------------------------------------------------
__global__ void hist_kernel(const int* __restrict__ etype) {
    __shared__ int h[TT];
    if (threadIdx.x < TT) h[threadIdx.x] = 0;
    __syncthreads();
    int e = blockIdx.x * blockDim.x + threadIdx.x;
    if (e < EE) atomicAdd(&h[etype[e]], 1);
    __syncthreads();
    if (threadIdx.x < TT) atomicAdd(&g_counts[threadIdx.x], h[threadIdx.x]);
}

// ---------------------------------------------------------------------------
// Kernel 2: bin edges by type (bases from final g_counts via local prefix)
// ---------------------------------------------------------------------------
__global__ void scatter_kernel(const int* __restrict__ etype,
                               const int* __restrict__ src,
                               const int* __restrict__ dst) {
    __shared__ int h[TT], base[TT], h2[TT];
    int e = blockIdx.x * blockDim.x + threadIdx.x;
    if (threadIdx.x < TT) { h[threadIdx.x] = 0; h2[threadIdx.x] = 0; }
    __syncthreads();
    int t = 0, s = 0, d = 0;
    bool valid = (e < EE);
    if (valid) {
        t = etype[e]; s = src[e]; d = dst[e];
        atomicAdd(&h[t], 1);
    }
    __syncthreads();
    if (threadIdx.x < TT) {
        int b = 0;
#pragma unroll
        for (int q = 0; q < TT; q++) {
            int c = g_counts[q];
            if (q < (int)threadIdx.x) b += c;
        }
        base[threadIdx.x] = b + atomicAdd(&g_cursor[threadIdx.x], h[threadIdx.x]);
    }
    __syncthreads();
    if (valid) {
        int pos = base[t] + atomicAdd(&h2[t], 1);
        g_src_s[pos] = s;
        g_dst_s[pos] = d;
    }
}

// ---------------------------------------------------------------------------
// Kernel 3: edge messages — EXACT R4 WINNER (142 us measured 3x).
// ---------------------------------------------------------------------------
#define EBLOCKS 148
#define ETHREADS 256
#define NWARP   (EBLOCKS * ETHREADS / 32)              // 1184
#define CHUNK   ((EE + NWARP - 1) / NWARP)             // 423

__global__ void __launch_bounds__(ETHREADS, 1)
edge_kernel(const float* __restrict__ features,
            const float* __restrict__ edge_emb) {
    __shared__ float4 sf[ETHREADS / 32][8][16];        // 8-slot ring per warp
    const unsigned FULL = 0xffffffffu;
    const int wib = threadIdx.x >> 5, lane = threadIdx.x & 31;

    int w = blockIdx.x * (ETHREADS / 32) + wib;
    long e0 = (long)w * CHUNK;
    if (e0 >= EE) return;
    long e1 = e0 + CHUNK;
    if (e1 > EE) e1 = EE;

    int bases[TT + 1];
    {
        int b = 0;
#pragma unroll
        for (int t = 0; t < TT; t++) { bases[t] = b; b += g_counts[t]; }
        bases[TT] = b;
    }

    ull wA[32], wB[32];  // rows 2*lane, 2*lane+1 of current type matrix
    long e = e0;
    int t = 0;
    while (e < e1) {
        while (bases[t + 1] <= e) t++;
        long seg_end = bases[t + 1] < e1 ? bases[t + 1] : e1;

        {
            const ulonglong2* pA = reinterpret_cast<const ulonglong2*>(
                edge_emb + (size_t)t * 4096 + (size_t)(2 * lane) * 64);
            const ulonglong2* pB = reinterpret_cast<const ulonglong2*>(
                edge_emb + (size_t)t * 4096 + (size_t)(2 * lane + 1) * 64);
#pragma unroll
            for (int q = 0; q < 16; q++) {
                ulonglong2 a = pA[q]; wA[2 * q] = a.x; wA[2 * q + 1] = a.y;
            }
#pragma unroll
            for (int q = 0; q < 16; q++) {
                ulonglong2 b = pB[q]; wB[2 * q] = b.x; wB[2 * q + 1] = b.y;
            }
        }

        for (long b0 = e; b0 < seg_end; b0 += 32) {
            int nb = (int)((seg_end - b0 < 32) ? (seg_end - b0) : 32);
            int my_s = 0, my_d = 0;
            if (lane < nb) {
                my_s = g_src_s[b0 + lane];
                my_d = g_dst_s[b0 + lane];
            }
#pragma unroll
            for (int j = 0; j < 6; j++) {
                if (j < nb) {
                    int s = __shfl_sync(FULL, my_s, j);
                    if (lane < 16) {
                        unsigned sp = (unsigned)__cvta_generic_to_shared(
                            &sf[wib][j & 7][lane]);
                        asm volatile("cp.async.cg.shared.global [%0], [%1], 16;"
                                     :: "r"(sp),
                                        "l"(features + (size_t)s * 64 + lane * 4));
                    }
                }
                asm volatile("cp.async.commit_group;");
            }
            for (int j = 0; j < nb; j++) {
                asm volatile("cp.async.wait_group 5;");
                __syncwarp();
                if (j + 6 < nb) {
                    int s = __shfl_sync(FULL, my_s, j + 6);
                    if (lane < 16) {
                        unsigned sp = (unsigned)__cvta_generic_to_shared(
                            &sf[wib][(j + 6) & 7][lane]);
                        asm volatile("cp.async.cg.shared.global [%0], [%1], 16;"
                                     :: "r"(sp),
                                        "l"(features + (size_t)s * 64 + lane * 4));
                    }
                }
                asm volatile("cp.async.commit_group;");

                int d = __shfl_sync(FULL, my_d, j);
                const ulonglong2* fp = reinterpret_cast<const ulonglong2*>(
                    &sf[wib][j & 7][0]);
                ull a0 = 0, a1 = 0, c0 = 0, c1 = 0;
#pragma unroll
                for (int q = 0; q < 16; q += 2) {
                    ulonglong2 f0 = fp[q], f1 = fp[q + 1];
                    fma2(a0, wA[2 * q],     f0.x); fma2(a0, wA[2 * q + 1], f0.y);
                    fma2(c0, wB[2 * q],     f0.x); fma2(c0, wB[2 * q + 1], f0.y);
                    fma2(a1, wA[2 * q + 2], f1.x); fma2(a1, wA[2 * q + 3], f1.y);
                    fma2(c1, wB[2 * q + 2], f1.x); fma2(c1, wB[2 * q + 3], f1.y);
                }
                float2 fa0 = asf2(a0), fa1 = asf2(a1);
                float2 fc0 = asf2(c0), fc1 = asf2(c1);
                float r0 = (fa0.x + fa0.y) + (fa1.x + fa1.y);
                float r1 = (fc0.x + fc0.y) + (fc1.x + fc1.y);
                float p0 = __shfl_xor_sync(FULL, r0, 1);
                float p1 = __shfl_xor_sync(FULL, r1, 1);
                if (!(lane & 1)) {
                    const float* op = g_reduced + (size_t)d * 64 + 2 * lane;
                    asm volatile("red.global.add.v4.f32 [%0], {%1, %2, %3, %4};"
                                 :: "l"(op), "f"(r0), "f"(r1), "f"(p0), "f"(p1)
                                 : "memory");
                }
            }
            asm volatile("cp.async.wait_group 0;");
            __syncwarp();
        }
        e = seg_end;
    }
}

// ---------------------------------------------------------------------------
// Kernel 4: GRU via tensor cores (fp16 inputs, fp32 accumulate).
// gates[128 nodes][256] = [reduced|features][128,128] @ W'^T, where W' rows:
//   g in [0,64):    [W_ih[g]      | W_hh[g]      ]   (r combined)
//   g in [64,128):  [W_ih[g]      | W_hh[g]      ]   (z combined)
//   g in [128,192): [W_ih[g]      | 0            ]   (i_n: W_ih row 128+(g-128)=g)
//   g in [192,256): [0            | W_hh[g-64]   ]   (h_n: W_hh row 128+(g-192)=g-64)
// Epilogue: r=sig(..), z=sig(..), n=tanh(i_n + r*h_n), h'=(1-z)n+z*h (h fp32),
// out = h'@W_out^T + b_out, fully fused.
// ---------------------------------------------------------------------------
#define MTILE 128
#define GTHREADS 256
#define NGB ((NN + MTILE - 1) / MTILE)        // 782
// smem: gates f32 [256][128] @0 (131072B), Xh half [128][136] @131072 (34816B),
//       Wh half [256][128] @165888 (65536B) -> total 231424B
#define GEMM_SMEM 231424

__global__ void __launch_bounds__(GTHREADS, 1)
gru_gemm_kernel(const float* __restrict__ features,
                const float* __restrict__ W_ih, const float* __restrict__ W_hh,
                const float* __restrict__ b_ih, const float* __restrict__ b_hh,
                const float* __restrict__ W_out, const float* __restrict__ b_out,
                float* __restrict__ out) {
    extern __shared__ char smem[];
    float*  gates_s = (float*)smem;                    // [256 gates][128 nodes]
    __half* Xh      = (__half*)(smem + 131072);        // [128][136]
    __half* Wh      = (__half*)(smem + 165888);        // [256][128]

    int tid  = threadIdx.x;
    int base = blockIdx.x * MTILE;

    // ---- X tile: [reduced | features] -> fp16 smem (zero-fill past NN) ----
    for (int idx = tid; idx < MTILE * 32; idx += GTHREADS) {
        int r = idx >> 5, q = idx & 31;
        int n = base + r;
        float4 v = make_float4(0.f, 0.f, 0.f, 0.f);
        if (n < NN) {
            v = (q < 16)
                ? reinterpret_cast<const float4*>(g_reduced + (size_t)n * 64)[q]
                : reinterpret_cast<const float4*>(features + (size_t)n * 64)[q - 16];
        }
        __half2* dst = reinterpret_cast<__half2*>(Xh + r * 136 + q * 4);
        dst[0] = __floats2half2_rn(v.x, v.y);
        dst[1] = __floats2half2_rn(v.z, v.w);
    }
    // ---- W' -> fp16 smem ----
    for (int idx = tid; idx < 256 * 128; idx += GTHREADS) {
        int g = idx >> 7, k = idx & 127;
        float w;
        if (g < 128) {
            w = (k < 64) ? W_ih[g * 64 + k] : W_hh[g * 64 + (k - 64)];
        } else if (g < 192) {
            w = (k < 64) ? W_ih[g * 64 + k] : 0.f;          // i_n: W_ih row g (=128+j)
        } else {
            w = (k < 64) ? 0.f : W_hh[(g - 64) * 64 + (k - 64)];  // h_n: W_hh row g-64
        }
        Wh[g * 128 + k] = __float2half_rn(w);
    }
    __syncthreads();

    // ---- GEMM: 8 warps, warp = 32 node-rows x 128 gate-cols ----
    int wid = tid >> 5;
    int wm = wid & 3;        // node tile: rows wm*32
    int wn = wid >> 2;       // gate half: cols wn*128
    wmma::fragment<wmma::accumulator, 16, 16, 16, float> acc[2][8];
#pragma unroll
    for (int i = 0; i < 2; i++)
#pragma unroll
        for (int j = 0; j < 8; j++) wmma::fill_fragment(acc[i][j], 0.f);

#pragma unroll 1
    for (int ks = 0; ks < 8; ks++) {
        wmma::fragment<wmma::matrix_a, 16, 16, 16, __half, wmma::row_major> a0, a1;
        wmma::load_matrix_sync(a0, Xh + (wm * 32) * 136 + ks * 16, 136);
        wmma::load_matrix_sync(a1, Xh + (wm * 32 + 16) * 136 + ks * 16, 136);
#pragma unroll
        for (int nt = 0; nt < 8; nt++) {
            wmma::fragment<wmma::matrix_b, 16, 16, 16, __half, wmma::col_major> b;
            wmma::load_matrix_sync(b, Wh + (wn * 128 + nt * 16) * 128 + ks * 16, 128);
            wmma::mma_sync(acc[0][nt], a0, b, acc[0][nt]);
            wmma::mma_sync(acc[1][nt], a1, b, acc[1][nt]);
        }
    }
    // Store transposed: gates_s[gate][node] (mem_col_major: (m,n)->ptr[m + n*ldm])
#pragma unroll
    for (int nt = 0; nt < 8; nt++) {
        wmma::store_matrix_sync(gates_s + (wn * 128 + nt * 16) * 128 + wm * 32,
                                acc[0][nt], 128, wmma::mem_col_major);
        wmma::store_matrix_sync(gates_s + (wn * 128 + nt * 16) * 128 + wm * 32 + 16,
                                acc[1][nt], 128, wmma::mem_col_major);
    }
    __syncthreads();

    // ---- repurpose Xh region for epilogue constants ----
    float* sWoT  = (float*)Xh;        // [64][16] W_out transposed
    float* sbih  = sWoT + 1024;       // 192
    float* sbhh  = sbih + 192;        // 192
    float* sbout = sbhh + 192;        // 16
    for (int i = tid; i < 1024; i += GTHREADS) {
        int j = i >> 4, c = i & 15;
        sWoT[j * 16 + c] = W_out[c * 64 + j];
    }
    for (int i = tid; i < 192; i += GTHREADS) { sbih[i] = b_ih[i]; sbhh[i] = b_hh[i]; }
    if (tid < 16) sbout[tid] = b_out[tid];
    __syncthreads();

    // ---- epilogue: thread t owns node base+t (t < 128) ----
    if (tid < MTILE) {
        int n = base + tid;
        if (n < NN) {
            const float4* hp = reinterpret_cast<const float4*>(features + (size_t)n * 64);
            float oacc[16];
#pragma unroll
            for (int c = 0; c < 16; c++) oacc[c] = sbout[c];
#pragma unroll 1
            for (int jq = 0; jq < 16; jq++) {
                float4 hv = hp[jq];
#pragma unroll
                for (int dj = 0; dj < 4; dj++) {
                    int j = jq * 4 + dj;
                    float rv  = gates_s[(j      ) * 128 + tid] + sbih[j]      + sbhh[j];
                    float zv  = gates_s[(64  + j) * 128 + tid] + sbih[64 + j] + sbhh[64 + j];
                    float inv = gates_s[(128 + j) * 128 + tid] + sbih[128 + j];
                    float hnv = gates_s[(192 + j) * 128 + tid] + sbhh[128 + j];
                    float r  = fast_sigmoid(rv);
                    float z  = fast_sigmoid(zv);
                    float ng = fast_tanh(inv + r * hnv);
                    float hj = (dj == 0) ? hv.x : (dj == 1) ? hv.y : (dj == 2) ? hv.z : hv.w;
                    float hnew = (1.f - z) * ng + z * hj;
                    const float* wo = sWoT + j * 16;
#pragma unroll
                    for (int c = 0; c < 16; c++) oacc[c] += wo[c] * hnew;
                }
            }
            float4* op = reinterpret_cast<float4*>(out + (size_t)n * 16);
#pragma unroll
            for (int q = 0; q < 4; q++)
                op[q] = make_float4(oacc[4 * q], oacc[4 * q + 1],
                                    oacc[4 * q + 2], oacc[4 * q + 3]);
        }
    }
}

// ---------------------------------------------------------------------------
extern "C" void kernel_launch(void* const* d_in, const int* in_sizes, int n_in,
                              void* d_out, int out_size) {
    const float* features = (const float*)d_in[0];
    const float* edge_emb = (const float*)d_in[1];
    const float* W_ih     = (const float*)d_in[2];
    const float* W_hh     = (const float*)d_in[3];
    const float* b_ih     = (const float*)d_in[4];
    const float* b_hh     = (const float*)d_in[5];
    const float* W_out    = (const float*)d_in[6];
    const float* b_out    = (const float*)d_in[7];
    const int*   etype    = (const int*)d_in[8];
    const int*   src      = (const int*)d_in[9];
    const int*   dst      = (const int*)d_in[10];
    float*       out      = (float*)d_out;

    cudaFuncSetAttribute(gru_gemm_kernel,
                         cudaFuncAttributeMaxDynamicSharedMemorySize, GEMM_SMEM);

    zero_kernel<<<(NN * MSGD / 4 + 255) / 256, 256>>>();
    hist_kernel<<<(EE + 511) / 512, 512>>>(etype);
    scatter_kernel<<<(EE + 511) / 512, 512>>>(etype, src, dst);
    edge_kernel<<<EBLOCKS, ETHREADS>>>(features, edge_emb);
    gru_gemm_kernel<<<NGB, GTHREADS, GEMM_SMEM>>>(features, W_ih, W_hh,
                                                  b_ih, b_hh, W_out, b_out, out);
}

// round 12
// speedup vs baseline: 1.1862x; 1.1862x over previous
#include <cuda_runtime.h>
#include <cuda_fp16.h>
#include <mma.h>
#include <math.h>

using namespace nvcuda;

#define NN   100000
#define EE   500000
#define TT   8
#define MSGD 64
#define HIDD 64
#define CC   16

typedef unsigned long long ull;

// ---------------------------------------------------------------------------
// Device scratch
// ---------------------------------------------------------------------------
__device__ __align__(16) float g_reduced[(size_t)NN * MSGD];
__device__ __align__(32) __half g_Wh[256 * 128];   // packed fp16 GRU weights
__device__ int g_counts[TT];
__device__ int g_cursor[TT];
__device__ int g_src_s[EE];
__device__ int g_dst_s[EE];

// ---------------------------------------------------------------------------
// Packed fp32x2 helpers (Blackwell FFMA2)
// ---------------------------------------------------------------------------
__device__ __forceinline__ void fma2(ull& d, ull a, ull b) {
    asm volatile("fma.rn.f32x2 %0, %1, %2, %0;" : "+l"(d) : "l"(a), "l"(b));
}
__device__ __forceinline__ float2 asf2(ull v) {
    float2 r;
    asm("mov.b64 {%0, %1}, %2;" : "=f"(r.x), "=f"(r.y) : "l"(v));
    return r;
}
__device__ __forceinline__ float fast_sigmoid(float x) {
    return __fdividef(1.f, 1.f + __expf(-x));
}
__device__ __forceinline__ float fast_tanh(float x) {
    return 1.f - __fdividef(2.f, __expf(2.f * x) + 1.f);
}

// ---------------------------------------------------------------------------
// Kernel 0: zero reduction buffer + reset counters
// ---------------------------------------------------------------------------
__global__ void zero_kernel() {
    int i = blockIdx.x * blockDim.x + threadIdx.x;
    if (i < NN * MSGD / 4) {
        reinterpret_cast<float4*>(g_reduced)[i] = make_float4(0.f, 0.f, 0.f, 0.f);
    }
    if (blockIdx.x == 0 && threadIdx.x < TT) {
        g_counts[threadIdx.x] = 0;
        g_cursor[threadIdx.x] = 0;
    }
}

// ---------------------------------------------------------------------------
// Kernel 0b: pack GRU weights to fp16 ONCE.
//   g in [0,64):    [W_ih[g] | W_hh[g]]        (r)
//   g in [64,128):  [W_ih[g] | W_hh[g]]        (z)
//   g in [128,192): [W_ih[g] | 0      ]        (i_n, W_ih row g = 128+j)
//   g in [192,256): [0       | W_hh[g-64]]     (h_n, W_hh row g-64 = 128+j)
// ---------------------------------------------------------------------------
__global__ void wprep_kernel(const float* __restrict__ W_ih,
                             const float* __restrict__ W_hh) {
    int idx = blockIdx.x * blockDim.x + threadIdx.x;
    if (idx >= 256 * 128) return;
    int g = idx >> 7, k = idx & 127;
    float w;
    if (g < 128) {
        w = (k < 64) ? W_ih[g * 64 + k] : W_hh[g * 64 + (k - 64)];
    } else if (g < 192) {
        w = (k < 64) ? W_ih[g * 64 + k] : 0.f;
    } else {
        w = (k < 64) ? 0.f : W_hh[(g - 64) * 64 + (k - 64)];
    }
    g_Wh[idx] = __float2half_rn(w);
}

// ---------------------------------------------------------------------------
// Kernel 1: per-block histogram of edge types
// ---------------------------------------------------------------------------
__global__ void hist_kernel(const int* __restrict__ etype) {
    __shared__ int h[TT];
    if (threadIdx.x < TT) h[threadIdx.x] = 0;
    __syncthreads();
    int e = blockIdx.x * blockDim.x + threadIdx.x;
    if (e < EE) atomicAdd(&h[etype[e]], 1);
    __syncthreads();
    if (threadIdx.x < TT) atomicAdd(&g_counts[threadIdx.x], h[threadIdx.x]);
}

// ---------------------------------------------------------------------------
// Kernel 2: bin edges by type
// ---------------------------------------------------------------------------
__global__ void scatter_kernel(const int* __restrict__ etype,
                               const int* __restrict__ src,
                               const int* __restrict__ dst) {
    __shared__ int h[TT], base[TT], h2[TT];
    int e = blockIdx.x * blockDim.x + threadIdx.x;
    if (threadIdx.x < TT) { h[threadIdx.x] = 0; h2[threadIdx.x] = 0; }
    __syncthreads();
    int t = 0, s = 0, d = 0;
    bool valid = (e < EE);
    if (valid) {
        t = etype[e]; s = src[e]; d = dst[e];
        atomicAdd(&h[t], 1);
    }
    __syncthreads();
    if (threadIdx.x < TT) {
        int b = 0;
#pragma unroll
        for (int q = 0; q < TT; q++) {
            int c = g_counts[q];
            if (q < (int)threadIdx.x) b += c;
        }
        base[threadIdx.x] = b + atomicAdd(&g_cursor[threadIdx.x], h[threadIdx.x]);
    }
    __syncthreads();
    if (valid) {
        int pos = base[t] + atomicAdd(&h2[t], 1);
        g_src_s[pos] = s;
        g_dst_s[pos] = d;
    }
}

// ---------------------------------------------------------------------------
// Kernel 3: edge messages — EXACT R4 WINNER (142 us measured 4x).
// ---------------------------------------------------------------------------
#define EBLOCKS 148
#define ETHREADS 256
#define NWARP   (EBLOCKS * ETHREADS / 32)              // 1184
#define CHUNK   ((EE + NWARP - 1) / NWARP)             // 423

__global__ void __launch_bounds__(ETHREADS, 1)
edge_kernel(const float* __restrict__ features,
            const float* __restrict__ edge_emb) {
    __shared__ float4 sf[ETHREADS / 32][8][16];
    const unsigned FULL = 0xffffffffu;
    const int wib = threadIdx.x >> 5, lane = threadIdx.x & 31;

    int w = blockIdx.x * (ETHREADS / 32) + wib;
    long e0 = (long)w * CHUNK;
    if (e0 >= EE) return;
    long e1 = e0 + CHUNK;
    if (e1 > EE) e1 = EE;

    int bases[TT + 1];
    {
        int b = 0;
#pragma unroll
        for (int t = 0; t < TT; t++) { bases[t] = b; b += g_counts[t]; }
        bases[TT] = b;
    }

    ull wA[32], wB[32];
    long e = e0;
    int t = 0;
    while (e < e1) {
        while (bases[t + 1] <= e) t++;
        long seg_end = bases[t + 1] < e1 ? bases[t + 1] : e1;

        {
            const ulonglong2* pA = reinterpret_cast<const ulonglong2*>(
                edge_emb + (size_t)t * 4096 + (size_t)(2 * lane) * 64);
            const ulonglong2* pB = reinterpret_cast<const ulonglong2*>(
                edge_emb + (size_t)t * 4096 + (size_t)(2 * lane + 1) * 64);
#pragma unroll
            for (int q = 0; q < 16; q++) {
                ulonglong2 a = pA[q]; wA[2 * q] = a.x; wA[2 * q + 1] = a.y;
            }
#pragma unroll
            for (int q = 0; q < 16; q++) {
                ulonglong2 b = pB[q]; wB[2 * q] = b.x; wB[2 * q + 1] = b.y;
            }
        }

        for (long b0 = e; b0 < seg_end; b0 += 32) {
            int nb = (int)((seg_end - b0 < 32) ? (seg_end - b0) : 32);
            int my_s = 0, my_d = 0;
            if (lane < nb) {
                my_s = g_src_s[b0 + lane];
                my_d = g_dst_s[b0 + lane];
            }
#pragma unroll
            for (int j = 0; j < 6; j++) {
                if (j < nb) {
                    int s = __shfl_sync(FULL, my_s, j);
                    if (lane < 16) {
                        unsigned sp = (unsigned)__cvta_generic_to_shared(
                            &sf[wib][j & 7][lane]);
                        asm volatile("cp.async.cg.shared.global [%0], [%1], 16;"
                                     :: "r"(sp),
                                        "l"(features + (size_t)s * 64 + lane * 4));
                    }
                }
                asm volatile("cp.async.commit_group;");
            }
            for (int j = 0; j < nb; j++) {
                asm volatile("cp.async.wait_group 5;");
                __syncwarp();
                if (j + 6 < nb) {
                    int s = __shfl_sync(FULL, my_s, j + 6);
                    if (lane < 16) {
                        unsigned sp = (unsigned)__cvta_generic_to_shared(
                            &sf[wib][(j + 6) & 7][lane]);
                        asm volatile("cp.async.cg.shared.global [%0], [%1], 16;"
                                     :: "r"(sp),
                                        "l"(features + (size_t)s * 64 + lane * 4));
                    }
                }
                asm volatile("cp.async.commit_group;");

                int d = __shfl_sync(FULL, my_d, j);
                const ulonglong2* fp = reinterpret_cast<const ulonglong2*>(
                    &sf[wib][j & 7][0]);
                ull a0 = 0, a1 = 0, c0 = 0, c1 = 0;
#pragma unroll
                for (int q = 0; q < 16; q += 2) {
                    ulonglong2 f0 = fp[q], f1 = fp[q + 1];
                    fma2(a0, wA[2 * q],     f0.x); fma2(a0, wA[2 * q + 1], f0.y);
                    fma2(c0, wB[2 * q],     f0.x); fma2(c0, wB[2 * q + 1], f0.y);
                    fma2(a1, wA[2 * q + 2], f1.x); fma2(a1, wA[2 * q + 3], f1.y);
                    fma2(c1, wB[2 * q + 2], f1.x); fma2(c1, wB[2 * q + 3], f1.y);
                }
                float2 fa0 = asf2(a0), fa1 = asf2(a1);
                float2 fc0 = asf2(c0), fc1 = asf2(c1);
                float r0 = (fa0.x + fa0.y) + (fa1.x + fa1.y);
                float r1 = (fc0.x + fc0.y) + (fc1.x + fc1.y);
                float p0 = __shfl_xor_sync(FULL, r0, 1);
                float p1 = __shfl_xor_sync(FULL, r1, 1);
                if (!(lane & 1)) {
                    const float* op = g_reduced + (size_t)d * 64 + 2 * lane;
                    asm volatile("red.global.add.v4.f32 [%0], {%1, %2, %3, %4};"
                                 :: "l"(op), "f"(r0), "f"(r1), "f"(p0), "f"(p1)
                                 : "memory");
                }
            }
            asm volatile("cp.async.wait_group 0;");
            __syncwarp();
        }
        e = seg_end;
    }
}

// ---------------------------------------------------------------------------
// Kernel 4: GRU via tensor cores. MTILE=64, 2 CTAs/SM, B from global (L1),
// all-thread epilogue (4 threads per node + shfl reduction).
// ---------------------------------------------------------------------------
#define MTILE 64
#define GSTR  72                              // gates smem stride (floats)
#define GTHREADS 256
#define NGB ((NN + MTILE - 1) / MTILE)        // 1563
// smem: gates f32 [256][GSTR] = 73728B, Xh half [64][136] = 17408B
#define GEMM_SMEM (73728 + 17408)

__global__ void __launch_bounds__(GTHREADS, 2)
gru_gemm_kernel(const float* __restrict__ features,
                const float* __restrict__ b_ih, const float* __restrict__ b_hh,
                const float* __restrict__ W_out, const float* __restrict__ b_out,
                float* __restrict__ out) {
    extern __shared__ char smem[];
    float*  gates_s = (float*)smem;                    // [256][GSTR]
    __half* Xh      = (__half*)(smem + 73728);         // [64][136]

    int tid  = threadIdx.x;
    int base = blockIdx.x * MTILE;

    // ---- X tile: [reduced | features] -> fp16 smem (zero-fill past NN) ----
    for (int idx = tid; idx < MTILE * 32; idx += GTHREADS) {
        int r = idx >> 5, q = idx & 31;
        int n = base + r;
        float4 v = make_float4(0.f, 0.f, 0.f, 0.f);
        if (n < NN) {
            v = (q < 16)
                ? reinterpret_cast<const float4*>(g_reduced + (size_t)n * 64)[q]
                : reinterpret_cast<const float4*>(features + (size_t)n * 64)[q - 16];
        }
        __half2* dst = reinterpret_cast<__half2*>(Xh + r * 136 + q * 4);
        dst[0] = __floats2half2_rn(v.x, v.y);
        dst[1] = __floats2half2_rn(v.z, v.w);
    }
    __syncthreads();

    // ---- GEMM: 8 warps; warp = 16 node-rows x 128 gate-cols; B from global ----
    {
        int wid = tid >> 5;
        int wm = wid & 3;        // node tile rows wm*16
        int wn = wid >> 2;       // gate half cols wn*128
        wmma::fragment<wmma::accumulator, 16, 16, 16, float> acc[8];
#pragma unroll
        for (int j = 0; j < 8; j++) wmma::fill_fragment(acc[j], 0.f);

#pragma unroll 1
        for (int ks = 0; ks < 8; ks++) {
            wmma::fragment<wmma::matrix_a, 16, 16, 16, __half, wmma::row_major> a;
            wmma::load_matrix_sync(a, Xh + (wm * 16) * 136 + ks * 16, 136);
#pragma unroll
            for (int nt = 0; nt < 8; nt++) {
                wmma::fragment<wmma::matrix_b, 16, 16, 16, __half, wmma::col_major> b;
                wmma::load_matrix_sync(b, g_Wh + (size_t)(wn * 128 + nt * 16) * 128 + ks * 16, 128);
                wmma::mma_sync(acc[nt], a, b, acc[nt]);
            }
        }
#pragma unroll
        for (int nt = 0; nt < 8; nt++) {
            wmma::store_matrix_sync(gates_s + (size_t)(wn * 128 + nt * 16) * GSTR + wm * 16,
                                    acc[nt], GSTR, wmma::mem_col_major);
        }
    }
    __syncthreads();

    // ---- epilogue constants overlay the Xh region ----
    float* sWoT  = (float*)Xh;        // [64][16]
    float* sb_r  = sWoT + 1024;       // 64
    float* sb_z  = sb_r + 64;         // 64
    float* sb_in = sb_z + 64;         // 64
    float* sb_hn = sb_in + 64;        // 64
    float* sbout = sb_hn + 64;        // 16
    for (int i = tid; i < 1024; i += GTHREADS) {
        int j = i >> 4, c = i & 15;
        sWoT[j * 16 + c] = W_out[c * 64 + j];
    }
    if (tid < 64) {
        sb_r[tid]  = b_ih[tid] + b_hh[tid];
        sb_z[tid]  = b_ih[64 + tid] + b_hh[64 + tid];
        sb_in[tid] = b_ih[128 + tid];
        sb_hn[tid] = b_hh[128 + tid];
    }
    if (tid < 16) sbout[tid] = b_out[tid];
    __syncthreads();

    // ---- epilogue: 4 threads per node, each owns 16 of 64 j's ----
    {
        int node = tid >> 2, part = tid & 3;
        int n = base + node;
        float oacc[16];
#pragma unroll
        for (int c = 0; c < 16; c++) oacc[c] = 0.f;

        if (n < NN) {
            const float4* hp = reinterpret_cast<const float4*>(features + (size_t)n * 64);
#pragma unroll
            for (int dq = 0; dq < 4; dq++) {
                int jq = part * 4 + dq;
                float4 hv = hp[jq];
#pragma unroll
                for (int dj = 0; dj < 4; dj++) {
                    int j = jq * 4 + dj;
                    float rv  = gates_s[(size_t)(j      ) * GSTR + node] + sb_r[j];
                    float zv  = gates_s[(size_t)(64  + j) * GSTR + node] + sb_z[j];
                    float inv = gates_s[(size_t)(128 + j) * GSTR + node] + sb_in[j];
                    float hnv = gates_s[(size_t)(192 + j) * GSTR + node] + sb_hn[j];
                    float r  = fast_sigmoid(rv);
                    float z  = fast_sigmoid(zv);
                    float ng = fast_tanh(inv + r * hnv);
                    float hj = (dj == 0) ? hv.x : (dj == 1) ? hv.y : (dj == 2) ? hv.z : hv.w;
                    float hnew = (1.f - z) * ng + z * hj;
                    const float* wo = sWoT + j * 16;
#pragma unroll
                    for (int c = 0; c < 16; c++) oacc[c] += wo[c] * hnew;
                }
            }
        }
        // combine 4 parts (lanes node*4..node*4+3 sit in one warp)
#pragma unroll
        for (int c = 0; c < 16; c++) {
            oacc[c] += __shfl_xor_sync(0xffffffffu, oacc[c], 1);
            oacc[c] += __shfl_xor_sync(0xffffffffu, oacc[c], 2);
        }
        if (part == 0 && n < NN) {
            float4* op = reinterpret_cast<float4*>(out + (size_t)n * 16);
#pragma unroll
            for (int q = 0; q < 4; q++)
                op[q] = make_float4(oacc[4 * q] + sbout[4 * q],
                                    oacc[4 * q + 1] + sbout[4 * q + 1],
                                    oacc[4 * q + 2] + sbout[4 * q + 2],
                                    oacc[4 * q + 3] + sbout[4 * q + 3]);
        }
    }
}

// ---------------------------------------------------------------------------
extern "C" void kernel_launch(void* const* d_in, const int* in_sizes, int n_in,
                              void* d_out, int out_size) {
    const float* features = (const float*)d_in[0];
    const float* edge_emb = (const float*)d_in[1];
    const float* W_ih     = (const float*)d_in[2];
    const float* W_hh     = (const float*)d_in[3];
    const float* b_ih     = (const float*)d_in[4];
    const float* b_hh     = (const float*)d_in[5];
    const float* W_out    = (const float*)d_in[6];
    const float* b_out    = (const float*)d_in[7];
    const int*   etype    = (const int*)d_in[8];
    const int*   src      = (const int*)d_in[9];
    const int*   dst      = (const int*)d_in[10];
    float*       out      = (float*)d_out;

    cudaFuncSetAttribute(gru_gemm_kernel,
                         cudaFuncAttributeMaxDynamicSharedMemorySize, GEMM_SMEM);

    zero_kernel<<<(NN * MSGD / 4 + 255) / 256, 256>>>();
    wprep_kernel<<<128, 256>>>(W_ih, W_hh);
    hist_kernel<<<(EE + 511) / 512, 512>>>(etype);
    scatter_kernel<<<(EE + 511) / 512, 512>>>(etype, src, dst);
    edge_kernel<<<EBLOCKS, ETHREADS>>>(features, edge_emb);
    gru_gemm_kernel<<<NGB, GTHREADS, GEMM_SMEM>>>(features, b_ih, b_hh,
                                                  W_out, b_out, out);
}